// round 4
// baseline (speedup 1.0000x reference)
#include <cuda_runtime.h>
#include <math.h>
#include <float.h>

#define B_ 8
#define H_ 128
#define W_ 128
#define G_ 64
#define C_ 20
#define GRID_ (B_ * H_)

// ---------------- device scratch ----------------
__device__ double   d_partial[GRID_][6];
__device__ int      d_nv[B_];
__device__ unsigned d_ticket;   // zero-init; self-resets via atomicInc wrap

// forced-rounding area so pass1/pass2 are bit-identical (no FMA contraction)
__device__ __forceinline__ float area_pad_f(float l, float r, float t, float d, float hm) {
    float a1 = __fadd_rn(__fmul_rn(l, hm), __fmul_rn(r, hm));
    float a2 = __fadd_rn(__fmul_rn(t, hm), __fmul_rn(d, hm));
    return __fadd_rn(__fmul_rn(a1, a2), __fmul_rn(__fsub_rn(1.0f, hm), 1e8f));
}

// ---------------- single fused kernel: one block per (b, y) row ----------------
__global__ __launch_bounds__(128) void fused_kernel(const float* __restrict__ kpt,
                                                    const float* __restrict__ preg,
                                                    const float* __restrict__ fpn,
                                                    const float* __restrict__ masks,
                                                    const float* __restrict__ gt,
                                                    const float* __restrict__ sy,
                                                    const float* __restrict__ sx,
                                                    float* __restrict__ out) {
    int bid = blockIdx.x;
    int b = bid >> 7, y = bid & 127;
    int x = threadIdx.x;

    __shared__ float         skpt[C_][W_], sfpn[C_][W_];   // transposed activations
    __shared__ float4        sbox[G_];
    __shared__ float         ssfx[G_], sisx[G_], seyarg[G_], scy[G_];
    __shared__ int           sseg[G_];
    __shared__ unsigned char sorder[G_];
    __shared__ int           sstart[C_ + 2];
    __shared__ int           sActG[G_], sActC[G_];
    __shared__ float         sActT[G_], sActD[G_];
    __shared__ unsigned      skp[W_];
    __shared__ int           s_nAct, s_nv, s_last;
    __shared__ double        sacc[6][4];

    float yg = y + 0.5f, xg = x + 0.5f;

    skp[x] = 0u;
    if (x == 0) s_nAct = 0;

    int kyr = 0, kxr = 0;
    // per-gt constants (threads 0..63, one gt each)
    if (x < G_) {
        const float* g7 = gt + (size_t)(b * G_ + x) * 7;
        float cy = g7[0], cx = g7[1];
        scy[x] = cy;
        sbox[x] = make_float4((g7[3] + 0.5f) * 0.25f,   // bx1
                              (g7[5] + 0.5f) * 0.25f,   // bx2
                              (g7[2] + 0.5f) * 0.25f,   // by1
                              (g7[4] + 0.5f) * 0.25f);  // by2
        ssfx[x] = floorf((cx + 0.5f) * 0.25f);
        float dy = (float)y - floorf((cy + 0.5f) * 0.25f);
        seyarg[x] = -dy * dy * (0.5f / sy[b * G_ + x]);
        sisx[x]   = 0.5f / sx[b * G_ + x];
        int cid = (int)g7[6] - 1;
        sseg[x] = (cid >= 0 && cid < C_) ? cid : C_;
        kyr = min(max((int)floorf(cy * 0.25f), 0), H_ - 1);
        kxr = min(max((int)floorf(cx * 0.25f), 0), W_ - 1);
    }

    // stage kpt/fpn rows (coalesced float4 -> transposed smem)
    size_t rowoff = (size_t)bid * W_;
    const float4* k4 = reinterpret_cast<const float4*>(kpt + rowoff * C_);
    const float4* f4 = reinterpret_cast<const float4*>(fpn + rowoff * C_);
#pragma unroll
    for (int i = x; i < W_ * C_ / 4; i += 128) {
        int xx = i / 5, c0 = (i % 5) * 4;
        float4 v = k4[i];
        skpt[c0][xx] = v.x; skpt[c0 + 1][xx] = v.y; skpt[c0 + 2][xx] = v.z; skpt[c0 + 3][xx] = v.w;
        float4 w = f4[i];
        sfpn[c0][xx] = w.x; sfpn[c0 + 1][xx] = w.y; sfpn[c0 + 2][xx] = w.z; sfpn[c0 + 3][xx] = w.w;
    }
    __syncthreads();

    // thread 0: nv (first-occurrence argmin) + counting sort by class
    if (x == 0) {
        float mn = scy[0]; int am = 0;
        for (int i = 1; i < G_; i++) if (scy[i] < mn) { mn = scy[i]; am = i; }
        s_nv = am;
        if (y == 0) d_nv[b] = am;
        int cnt[C_ + 1];
        for (int c = 0; c <= C_; c++) cnt[c] = 0;
        for (int i = 0; i < am; i++) cnt[sseg[i]]++;
        int run = 0;
        for (int c = 0; c <= C_; c++) { sstart[c] = run; run += cnt[c]; }
        sstart[C_ + 1] = run;
        int pos[C_ + 1];
        for (int c = 0; c <= C_; c++) pos[c] = sstart[c];
        for (int i = 0; i < am; i++) sorder[pos[sseg[i]]++] = (unsigned char)i;
    }
    __syncthreads();

    int nv = s_nv;
    // row compaction + kp scatter
    if (x < nv) {
        float4 bb = sbox[x];
        float t = yg - bb.z, dd = bb.w - yg;
        if (t > 0.f && dd > 0.f) {
            int a = atomicAdd(&s_nAct, 1);
            sActG[a] = x; sActT[a] = t; sActD[a] = dd; sActC[a] = sseg[x];
        }
        if (sseg[x] < C_ && kyr == y)
            atomicOr(&skp[kxr], 1u << sseg[x]);
    }
    __syncthreads();

    int nA = s_nAct;
    const float* mrow = masks + rowoff * G_ + (size_t)x * G_;

    // ---- pass 1 (compacted): loc, area_min ----
    float area_min = 1e8f;   // nv < G_ always => a hm=0 entry exists
    float loc = 0.f;
    for (int a = 0; a < nA; a++) {
        int g = sActG[a];
        float4 bb = sbox[g];
        float l = xg - bb.x, r = bb.y - xg;
        float m = __ldg(&mrow[g]);
        float hm = (l > 0.f && r > 0.f) ? m : 0.f;
        loc = fmaxf(loc, hm);
        area_min = fminf(area_min, area_pad_f(l, r, sActT[a], sActD[a], hm));
    }

    // ---- pass 2 (compacted): dist-mask maxima + per-class hg bitmask ----
    float dl = 0, dr = 0, dt = 0, db = 0;
    unsigned hgb = 0;
    for (int a = 0; a < nA; a++) {
        int g = sActG[a];
        float4 bb = sbox[g];
        float l = xg - bb.x, r = bb.y - xg;
        float t = sActT[a], d = sActD[a];
        float m = __ldg(&mrow[g]);
        float hm = (l > 0.f && r > 0.f) ? m : 0.f;
        float ap = area_pad_f(l, r, t, d, hm);
        if (ap == area_min) {
            dl = fmaxf(dl, l * hm * loc);
            dr = fmaxf(dr, r * hm * loc);
            dt = fmaxf(dt, t * hm * loc);
            db = fmaxf(db, d * hm * loc);
            hgb |= 1u << sActC[a];
        }
    }
    if (loc == 0.f) hgb = 0;

    // ---- pass 3: per-class gaussian max + fused focal losses ----
    float iou_red = 0.f, grav = 0.f, hpos = 0.f, hneg = 0.f, shg = 0.f;
    unsigned kb = skp[x];
    float xf = (float)x;
    for (int c = 0; c <= C_; c++) {
        float rg = 0.f;
        int j1 = sstart[c + 1];
        for (int j = sstart[c]; j < j1; j++) {
            int g = sorder[j];
            float dx = xf - ssfx[g];
            float red = __expf(fmaf(-dx * dx, sisx[g], seyarg[g]));
            rg = fmaxf(rg, red);
        }
        iou_red = fmaxf(iou_red, rg);
        if (c < C_) {
            float hg = ((hgb >> c) & 1u) ? loc : 0.f;
            float p  = fminf(fmaxf(skpt[c][x], -30.f), 30.f);
            float e1 = __expf(-p);
            float L1 = __logf(1.f + e1);            // -log_sigmoid(p)
            float iv = __fdividef(1.f, 1.f + e1);   // sigmoid(p)
            float om = e1 * iv;
            float q  = 1.f - rg; q = q * q; q = q * q;
            float neg = q * iv * iv * (p + L1);
            float pos = om * om * L1;
            grav += ((kb >> c) & 1u) ? pos : neg;
            float f   = fminf(fmaxf(sfpn[c][x], -30.f), 30.f);
            float e2  = __expf(-f);
            float L2  = __logf(1.f + e2);
            float iv2 = __fdividef(1.f, 1.f + e2);
            float om2 = e2 * iv2;
            hpos += om2 * om2 * L2 * hg;
            hneg += iv2 * iv2 * (f + L2);
            shg  += hg;
        }
    }

    // ---- IoU term ----
    float4 pv = reinterpret_cast<const float4*>(preg)[rowoff + x];
    float pl = pv.x, pr = pv.y, pt = pv.z, pb = pv.w;
    float inter = (fminf(dl, pl) + fminf(dr, pr)) * (fminf(dt, pt) + fminf(db, pb));
    float uni   = (dl + dr) * (dt + db) + (pl + pr) * (pt + pb) - inter;
    float iou   = inter / (uni + 1e-12f);
    float iou_t = -__logf(iou + 1e-12f) * loc * (iou_red * 4.f + 1.f);

    // ---- deterministic block reduction of 6 partials ----
    double v[6] = { (double)iou_t, (double)loc, (double)grav,
                    (double)hpos * 10.0, (double)hneg * 10.0, (double)shg };
#pragma unroll
    for (int off = 16; off; off >>= 1)
#pragma unroll
        for (int k = 0; k < 6; k++) v[k] += __shfl_down_sync(0xffffffffu, v[k], off);
    int w = x >> 5, lane = x & 31;
    if (lane == 0)
#pragma unroll
        for (int k = 0; k < 6; k++) sacc[k][w] = v[k];
    __syncthreads();
    if (x == 0) {
#pragma unroll
        for (int k = 0; k < 6; k++)
            d_partial[bid][k] = sacc[k][0] + sacc[k][1] + sacc[k][2] + sacc[k][3];
        __threadfence();
        unsigned old = atomicInc(&d_ticket, GRID_ - 1);   // wraps to 0 -> self-reset
        s_last = (old == GRID_ - 1);
    }
    __syncthreads();

    // ---- last block: deterministic final combine ----
    if (s_last) {
        __threadfence();
        int t = x;   // thread t = row t
        double tot = 0.0;
        for (int bb = 0; bb < B_; bb++) {
            double u[6];
#pragma unroll
            for (int k = 0; k < 6; k++) u[k] = d_partial[bb * H_ + t][k];
#pragma unroll
            for (int off = 16; off; off >>= 1)
#pragma unroll
                for (int k = 0; k < 6; k++) u[k] += __shfl_down_sync(0xffffffffu, u[k], off);
            __syncthreads();
            if ((t & 31) == 0)
#pragma unroll
                for (int k = 0; k < 6; k++) sacc[k][t >> 5] = u[k];
            __syncthreads();
            if (t == 0) {
                double iouS  = sacc[0][0] + sacc[0][1] + sacc[0][2] + sacc[0][3];
                double slocS = sacc[1][0] + sacc[1][1] + sacc[1][2] + sacc[1][3];
                double gravS = sacc[2][0] + sacc[2][1] + sacc[2][2] + sacc[2][3];
                double hposS = sacc[3][0] + sacc[3][1] + sacc[3][2] + sacc[3][3];
                double hnegS = sacc[4][0] + sacc[4][1] + sacc[4][2] + sacc[4][3];
                double shgS  = sacc[5][0] + sacc[5][1] + sacc[5][2] + sacc[5][3];
                double HWC = (double)(H_ * W_ * C_);
                double hm_loss = hnegS / (HWC - shgS);
                bool cond = (shgS != 0.0);
                double hm2 = hm_loss + hposS / (cond ? shgS : 1.0);
                double safe_loc = (slocS > 0.0) ? slocS : 1.0;
                double iou_out = cond ? (iouS / safe_loc) : 0.0;
                double nvf = (d_nv[bb] > 1) ? (double)d_nv[bb] : 1.0;
                double grav_out = cond ? (gravS / nvf) : 0.0;
                tot += cond ? (iou_out + grav_out + hm2) : hm_loss;
            }
        }
        if (t == 0) out[0] = (float)(tot * (1.0 / B_));
    }
}

// ---------------- launch ----------------
extern "C" void kernel_launch(void* const* d_in, const int* in_sizes, int n_in,
                              void* d_out, int out_size) {
    const float* keypoints = (const float*)d_in[0];
    const float* preg      = (const float*)d_in[1];
    const float* fpn       = (const float*)d_in[2];
    const float* gt        = (const float*)d_in[3];
    const float* masks     = (const float*)d_in[4];
    const float* sy        = (const float*)d_in[5];
    const float* sx        = (const float*)d_in[6];
    (void)in_sizes; (void)n_in; (void)out_size;

    fused_kernel<<<GRID_, 128>>>(keypoints, preg, fpn, masks, gt, sy, sx, (float*)d_out);
}

// round 6
// speedup vs baseline: 1.4869x; 1.4869x over previous
#include <cuda_runtime.h>
#include <math.h>
#include <float.h>

#define B_ 8
#define H_ 128
#define W_ 128
#define G_ 64
#define C_ 20
#define PAD_ 22
#define GRID_ (B_ * H_)

__device__ double   d_partial[GRID_][6];
__device__ int      d_nv[B_];
__device__ unsigned d_ticket;   // zero-init; self-resets via atomicInc wrap

__global__ __launch_bounds__(128) void fused_kernel(const float* __restrict__ kpt,
                                                    const float* __restrict__ preg,
                                                    const float* __restrict__ fpn,
                                                    const float* __restrict__ masks,
                                                    const float* __restrict__ gt,
                                                    const float* __restrict__ sy,
                                                    const float* __restrict__ sx,
                                                    float* __restrict__ out) {
    int bid = blockIdx.x;
    int b = bid >> 7, y = bid & 127;
    int x = threadIdx.x;

    __shared__ float4   sbox[G_];
    __shared__ float    ssfx[G_], sisx[G_], seyarg[G_], scyv[G_];
    __shared__ int      sseg[G_];
    __shared__ int      sActG[G_];            // packed g | seg<<8
    __shared__ unsigned skp[W_], shgb[W_];
    __shared__ float    sloc[W_];
    __shared__ float    srg[W_][PAD_];        // per-pixel per-class gaussian max
    __shared__ int      s_nAct, s_nv, s_last;
    __shared__ float    scand[2];
    __shared__ int      scandi[2];
    __shared__ double   sacc[6][4];

    float yg = y + 0.5f, xg = x + 0.5f;

    // ---- phase A: init + per-gt constants ----
    skp[x] = 0u;
#pragma unroll
    for (int c = 0; c < C_; c++) srg[x][c] = 0.f;

    int kyr = -1, kxr = 0;
    float cyv = 0.f;
    if (x < G_) {
        const float* g7 = gt + (size_t)(b * G_ + x) * 7;
        float cy = g7[0], cx = g7[1];
        cyv = cy;
        scyv[x] = cy;
        sbox[x] = make_float4((g7[3] + 0.5f) * 0.25f,   // bx1
                              (g7[5] + 0.5f) * 0.25f,   // bx2
                              (g7[2] + 0.5f) * 0.25f,   // by1
                              (g7[4] + 0.5f) * 0.25f);  // by2
        ssfx[x] = floorf((cx + 0.5f) * 0.25f);
        float dy = (float)y - floorf((cy + 0.5f) * 0.25f);
        seyarg[x] = -dy * dy * (0.5f / sy[b * G_ + x]);
        sisx[x]   = 0.5f / sx[b * G_ + x];
        int cid = (int)g7[6] - 1;
        sseg[x] = (cid >= 0 && cid < C_) ? cid : C_;
        kyr = min(max((int)floorf(cy * 0.25f), 0), H_ - 1);
        kxr = min(max((int)floorf(cx * 0.25f), 0), W_ - 1);
    }
    __syncthreads();

    // ---- parallel first-occurrence argmin over gts 0..63 (2 warps) ----
    if (x < G_) {
        float v = cyv; int idx = x;
#pragma unroll
        for (int off = 16; off; off >>= 1) {
            float ov = __shfl_down_sync(0xffffffffu, v, off);
            int   oi = __shfl_down_sync(0xffffffffu, idx, off);
            if (ov < v || (ov == v && oi < idx)) { v = ov; idx = oi; }
        }
        if ((x & 31) == 0) { scand[x >> 5] = v; scandi[x >> 5] = idx; }
    }
    __syncthreads();
    if (x == 0) {
        float v0 = scand[0], v1 = scand[1];
        int   i0 = scandi[0], i1 = scandi[1];
        int am = (v1 < v0 || (v1 == v0 && i1 < i0)) ? i1 : i0;
        s_nv = am;
        s_nAct = 0;
        if (y == 0) d_nv[b] = am;
    }
    __syncthreads();
    int nv = s_nv;

    // ---- compaction of row-active gts + kp scatter ----
    if (x < nv) {
        float4 bb = sbox[x];
        float t = yg - bb.z, dd = bb.w - yg;
        if (t > 0.f && dd > 0.f) {
            int a = atomicAdd(&s_nAct, 1);
            sActG[a] = x | (sseg[x] << 8);
        }
        if (sseg[x] < C_ && kyr == y)
            atomicOr(&skp[kxr], 1u << sseg[x]);
    }
    __syncthreads();

    // ---- geometry: single pass with exact tie-merging argmin ----
    int nA = s_nAct;
    size_t rowoff = (size_t)bid * W_;
    const float* mrow = masks + (rowoff + x) * G_;
    float area_min = 1e8f, loc = 0.f;
    float ml = 0.f, mr = 0.f, mt = 0.f, mb = 0.f;
    unsigned hgb = 0u;
    for (int a = 0; a < nA; a++) {
        int pk = sActG[a];
        int g = pk & 255, cg = pk >> 8;
        float4 bb = sbox[g];
        float l = xg - bb.x, r = bb.y - xg, t = yg - bb.z, d = bb.w - yg;
        float m = __ldg(&mrow[g]);
        float hm = (l > 0.f && r > 0.f) ? m : 0.f;
        loc = fmaxf(loc, hm);
        float lh = l * hm, rh = r * hm, th = t * hm, dh = d * hm;
        float ap = (lh + rh) * (th + dh) + (1.f - hm) * 1e8f;
        if (ap < area_min) {
            area_min = ap; ml = lh; mr = rh; mt = th; mb = dh; hgb = 1u << cg;
        } else if (ap == area_min) {
            ml = fmaxf(ml, lh); mr = fmaxf(mr, rh);
            mt = fmaxf(mt, th); mb = fmaxf(mb, dh);
            hgb |= 1u << cg;
        }
    }
    if (loc == 0.f) hgb = 0u;
    float dl = ml * loc, dr = mr * loc, dt = mt * loc, db = mb * loc;

    // ---- gaussian scan: iou_red + per-class scatter-max into srg ----
    float iou_red = 0.f, xf = (float)x;
    for (int g = 0; g < nv; g++) {
        float dxx = xf - ssfx[g];
        float red = __expf(fmaf(-dxx * dxx, sisx[g], seyarg[g]));
        iou_red = fmaxf(iou_red, red);
        int c = sseg[g];
        if (c < C_) srg[x][c] = fmaxf(srg[x][c], red);
    }
    sloc[x] = loc;
    shgb[x] = hgb;
    __syncthreads();

    // ---- IoU term (thread = pixel x) ----
    float4 pv = reinterpret_cast<const float4*>(preg)[rowoff + x];
    float inter = (fminf(dl, pv.x) + fminf(dr, pv.y)) * (fminf(dt, pv.z) + fminf(db, pv.w));
    float uni   = (dl + dr) * (dt + db) + (pv.x + pv.y) * (pv.z + pv.w) - inter;
    float iou_t = -__logf(inter / (uni + 1e-12f) + 1e-12f) * loc * (iou_red * 4.f + 1.f);

    // ---- focal losses: flat coalesced loop over W*C elements ----
    float grav = 0.f, hpos = 0.f, hneg = 0.f, shg = 0.f;
    const float4* kr4 = reinterpret_cast<const float4*>(kpt + rowoff * C_);
    const float4* fr4 = reinterpret_cast<const float4*>(fpn + rowoff * C_);
#pragma unroll
    for (int ch = 0; ch < (W_ * C_ / 4) / 128; ch++) {
        int i4 = ch * 128 + x;
        float4 kv = __ldg(&kr4[i4]);
        float4 fv = __ldg(&fr4[i4]);
        float ka[4] = { kv.x, kv.y, kv.z, kv.w };
        float fa[4] = { fv.x, fv.y, fv.z, fv.w };
#pragma unroll
        for (int e = 0; e < 4; e++) {
            int i = i4 * 4 + e;
            int xx = i / C_, cc = i - xx * C_;
            float rg = srg[xx][cc];
            float hg = ((shgb[xx] >> cc) & 1u) ? sloc[xx] : 0.f;
            // gravity focal
            float p  = fminf(fmaxf(ka[e], -30.f), 30.f);
            float e1 = __expf(-p);
            float L1 = __logf(1.f + e1);
            float iv = __fdividef(1.f, 1.f + e1);
            float om = e1 * iv;
            float q  = 1.f - rg; q = q * q; q = q * q;
            grav += ((skp[xx] >> cc) & 1u) ? (om * om * L1)
                                           : (q * iv * iv * (p + L1));
            // heatmap focal
            float f   = fminf(fmaxf(fa[e], -30.f), 30.f);
            float e2  = __expf(-f);
            float L2  = __logf(1.f + e2);
            float iv2 = __fdividef(1.f, 1.f + e2);
            float om2 = e2 * iv2;
            hpos += om2 * om2 * L2 * hg;
            hneg += iv2 * iv2 * (f + L2);
            shg  += hg;
        }
    }

    // ---- deterministic block reduction (float tree, double store) ----
    float v[6] = { iou_t, loc, grav, hpos * 10.f, hneg * 10.f, shg };
#pragma unroll
    for (int off = 16; off; off >>= 1)
#pragma unroll
        for (int k = 0; k < 6; k++) v[k] += __shfl_down_sync(0xffffffffu, v[k], off);
    int w = x >> 5, lane = x & 31;
    __syncthreads();
    if (lane == 0)
#pragma unroll
        for (int k = 0; k < 6; k++) sacc[k][w] = (double)v[k];
    __syncthreads();
    if (x == 0) {
#pragma unroll
        for (int k = 0; k < 6; k++)
            d_partial[bid][k] = sacc[k][0] + sacc[k][1] + sacc[k][2] + sacc[k][3];
        __threadfence();
        unsigned old = atomicInc(&d_ticket, GRID_ - 1);   // wraps -> self-reset
        s_last = (old == GRID_ - 1);
    }
    __syncthreads();

    // ---- last block: deterministic final combine ----
    if (s_last) {
        __threadfence();
        int t = x;
        double tot = 0.0;
        for (int bb = 0; bb < B_; bb++) {
            double u[6];
#pragma unroll
            for (int k = 0; k < 6; k++) u[k] = d_partial[bb * H_ + t][k];
#pragma unroll
            for (int off = 16; off; off >>= 1)
#pragma unroll
                for (int k = 0; k < 6; k++) u[k] += __shfl_down_sync(0xffffffffu, u[k], off);
            __syncthreads();
            if ((t & 31) == 0)
#pragma unroll
                for (int k = 0; k < 6; k++) sacc[k][t >> 5] = u[k];
            __syncthreads();
            if (t == 0) {
                double iouS  = sacc[0][0] + sacc[0][1] + sacc[0][2] + sacc[0][3];
                double slocS = sacc[1][0] + sacc[1][1] + sacc[1][2] + sacc[1][3];
                double gravS = sacc[2][0] + sacc[2][1] + sacc[2][2] + sacc[2][3];
                double hposS = sacc[3][0] + sacc[3][1] + sacc[3][2] + sacc[3][3];
                double hnegS = sacc[4][0] + sacc[4][1] + sacc[4][2] + sacc[4][3];
                double shgS  = sacc[5][0] + sacc[5][1] + sacc[5][2] + sacc[5][3];
                double HWC = (double)(H_ * W_ * C_);
                double hm_loss = hnegS / (HWC - shgS);
                bool cond = (shgS != 0.0);
                double hm2 = hm_loss + hposS / (cond ? shgS : 1.0);
                double safe_loc = (slocS > 0.0) ? slocS : 1.0;
                double iou_out = cond ? (iouS / safe_loc) : 0.0;
                double nvf = (d_nv[bb] > 1) ? (double)d_nv[bb] : 1.0;
                double grav_out = cond ? (gravS / nvf) : 0.0;
                tot += cond ? (iou_out + grav_out + hm2) : hm_loss;
            }
        }
        if (t == 0) out[0] = (float)(tot * (1.0 / B_));
    }
}

// ---------------- launch ----------------
extern "C" void kernel_launch(void* const* d_in, const int* in_sizes, int n_in,
                              void* d_out, int out_size) {
    const float* keypoints = (const float*)d_in[0];
    const float* preg      = (const float*)d_in[1];
    const float* fpn       = (const float*)d_in[2];
    const float* gt        = (const float*)d_in[3];
    const float* masks     = (const float*)d_in[4];
    const float* sy        = (const float*)d_in[5];
    const float* sx        = (const float*)d_in[6];
    (void)in_sizes; (void)n_in; (void)out_size;

    fused_kernel<<<GRID_, 128>>>(keypoints, preg, fpn, masks, gt, sy, sx, (float*)d_out);
}